// round 14
// baseline (speedup 1.0000x reference)
#include <cuda_runtime.h>
#include <cuda_bf16.h>
#include <cuda_fp8.h>
#include <cuda_fp16.h>
#include <math.h>

#define T  4
#define Bb 16
#define C  512
#define HW 256
#define Nn 256
#define C3 1536
#define HID 2048
#define NH 8
#define Dd 64
#define TB (T*Bb)            // 64
#define BN (Bb*Nn)           // 4096
#define TBN (T*Bb*Nn)        // 16384
#define XSZ (T*Bb*C*HW)      // 8388608

// ---------------- scratch (no cudaMalloc allowed) ----------------
__device__ float         g_xc[XSZ];       // x + pos         [T,B,C,HW]
__device__ float         g_xt[XSZ];       // residual stream [T,B,N,C]
__device__ unsigned char g_qkvs[TBN*C3];  // q/k/v spikes    [T,B,N,3C]
__device__ float         g_attn[XSZ];     // attn out        [T,B,N,C]
__device__ __align__(16) unsigned char g_wq8 [C*C3];   // fp8 [cin][3C]
__device__ __align__(16) unsigned char g_wf18[C*HID];  // fp8 [cin][HID]
__device__ __align__(16) __nv_bfloat16 g_wp [C*C];     // bf16 [cin][C]
__device__ __align__(16) __nv_bfloat16 g_wf2[HID*C];   // bf16 [hid][C]

__device__ __forceinline__ float sigm(float w){ return 1.f/(1.f+expf(-w)); }

// accumulate 4 fp8 weights into two half2 accumulators (5 instrs total)
__device__ __forceinline__ void acc8(unsigned u, __half2& A, __half2& B){
    __half2_raw h0 = __nv_cvt_fp8x2_to_halfraw2((__nv_fp8x2_storage_t)(u & 0xFFFFu), __NV_E4M3);
    __half2_raw h1 = __nv_cvt_fp8x2_to_halfraw2((__nv_fp8x2_storage_t)(u >> 16),     __NV_E4M3);
    A = __hadd2(A, *reinterpret_cast<__half2*>(&h0));
    B = __hadd2(B, *reinterpret_cast<__half2*>(&h1));
}

// ---------- single kernel: all 4 weight transposes (fp32 -> fp8/bf16) ----
__global__ void k_wt_all(const float* __restrict__ qkv_w, const float* __restrict__ proj_w,
                         const float* __restrict__ fc1_w, const float* __restrict__ fc2_w){
    __shared__ float tile[32][33];
    int bid = blockIdx.x;
    const float* src;  int nR, nC, local, mode;
    if      (bid < 768) { src = qkv_w;  nR = 1536; nC = 512;  local = bid;        mode = 0; }
    else if (bid < 1024){ src = proj_w; nR = 512;  nC = 512;  local = bid - 768;  mode = 1; }
    else if (bid < 2048){ src = fc1_w;  nR = 2048; nC = 512;  local = bid - 1024; mode = 2; }
    else                { src = fc2_w;  nR = 512;  nC = 2048; local = bid - 2048; mode = 3; }
    int tpr = nC >> 5;
    int tx = local % tpr, ty = local / tpr;
    int cx = tx*32 + threadIdx.x;
    int ry = ty*32 + threadIdx.y;
    tile[threadIdx.y][threadIdx.x] = src[(size_t)ry*nC + cx];
    __syncthreads();
    int ox = ty*32 + threadIdx.x;   // within nR
    int oy = tx*32 + threadIdx.y;   // within nC
    float v = tile[threadIdx.x][threadIdx.y];
    size_t di = (size_t)oy*nR + ox;
    if      (mode == 0) g_wq8 [di] = __nv_cvt_float_to_fp8(v, __NV_SATFINITE, __NV_E4M3);
    else if (mode == 1) g_wp  [di] = __float2bfloat16(v);
    else if (mode == 2) g_wf18[di] = __nv_cvt_float_to_fp8(v, __NV_SATFINITE, __NV_E4M3);
    else                g_wf2 [di] = __float2bfloat16(v);
}

// ---------- fused lif(x) + depthwise 3x3 conv + residual -----------------
__global__ void k_convf(const float* __restrict__ x, const float* __restrict__ conv_w,
                        const float* __restrict__ conv_b, const float* __restrict__ lifw,
                        float* __restrict__ xc){
    __shared__ float xs[T][324];
    __shared__ unsigned char ss[T][324];
    int bc = blockIdx.x;  int b = bc >> 9;  int c = bc & 511;
    int tid = threadIdx.x;
    float decay = sigm(lifw[0]);
    for (int i = tid; i < 324; i += 256){
        int y = i/18 - 1, xx = i%18 - 1;
        bool in = (y>=0 && y<16 && xx>=0 && xx<16);
        int p = y*16 + xx;
        #pragma unroll
        for (int t=0; t<T; t++)
            xs[t][i] = in ? x[((size_t)(t*Bb+b)*C + c)*HW + p] : 0.f;
    }
    __syncthreads();
    for (int i = tid; i < 324; i += 256){
        float v = 0.f;
        #pragma unroll
        for (int t=0; t<T; t++){
            float xv = xs[t][i];
            v = v + (xv - v)*decay;
            unsigned char s = (v >= 1.0f);
            if (s) v = 0.f;
            ss[t][i] = s;
        }
    }
    __syncthreads();
    int py = tid >> 4, px = tid & 15;
    float w[9];
    #pragma unroll
    for (int j=0;j<9;j++) w[j] = conv_w[c*9 + j];
    float cb = conv_b[c];
    #pragma unroll
    for (int t=0; t<T; t++){
        float acc = 0.f;
        #pragma unroll
        for (int ky=0; ky<3; ky++)
            #pragma unroll
            for (int kx=0; kx<3; kx++)
                acc += (float)ss[t][(py+ky)*18 + px+kx] * w[ky*3+kx];
        xc[((size_t)(t*Bb+b)*C + c)*HW + tid] = xs[t][(py+1)*18 + px+1] + acc + cb;
    }
}

// ---------- batched 2D fp32 transpose (per z-slice) ----------------------
__global__ void k_tr(const float* __restrict__ src, float* __restrict__ dst,
                     int rows, int cols){
    __shared__ float tile[32][33];
    int z = blockIdx.z;
    const float* s = src + (size_t)z*rows*cols;
    float*       d = dst + (size_t)z*rows*cols;
    int xx = blockIdx.x*32 + threadIdx.x;
    int yy = blockIdx.y*32 + threadIdx.y;
    tile[threadIdx.y][threadIdx.x] = s[(size_t)yy*cols + xx];
    __syncthreads();
    int x2 = blockIdx.y*32 + threadIdx.x;
    int y2 = blockIdx.x*32 + threadIdx.y;
    d[(size_t)y2*rows + x2] = tile[threadIdx.x][threadIdx.y];
}

// ---------- fused single-pass (sum, sumsq) block reduction ---------------
// red must hold 2*34 floats; slot in {0,1} double-buffers so no trailing sync
__device__ __forceinline__ float2 bsum2(float a, float q, float* red, int slot){
    float* r = red + slot*34;
    #pragma unroll
    for (int off=16; off; off>>=1){
        a += __shfl_down_sync(0xffffffffu, a, off);
        q += __shfl_down_sync(0xffffffffu, q, off);
    }
    int lane = threadIdx.x & 31, w = threadIdx.x >> 5;
    if (lane==0){ r[w] = a; r[17+w] = q; }
    __syncthreads();
    if (w==0){
        float s  = (lane < 16) ? r[lane]     : 0.f;
        float sq = (lane < 16) ? r[17+lane]  : 0.f;
        #pragma unroll
        for (int off=8; off; off>>=1){
            s  += __shfl_down_sync(0xffffffffu, s,  off);
            sq += __shfl_down_sync(0xffffffffu, sq, off);
        }
        if (lane==0){ r[16] = s; r[33] = sq; }
    }
    __syncthreads();
    return make_float2(r[16], r[33]);
}

// warp-0 builds ordered active-channel list from 16-word mask -------------
__device__ __forceinline__ void build_list(const unsigned* mask, int* list, int* s_cnt){
    int tid = threadIdx.x;
    if (tid < 32){
        unsigned wv = (tid < 16) ? mask[tid] : 0u;
        int c = __popc(wv);
        int inc = c;
        #pragma unroll
        for (int off=1; off<32; off<<=1){
            int v = __shfl_up_sync(0xffffffffu, inc, off);
            if (tid >= off) inc += v;
        }
        int idx = inc - c;
        while (wv){ int b = __ffs(wv)-1; wv &= wv-1; list[idx++] = (tid<<5) + b; }
        if (tid == 31) *s_cnt = inc;
    }
    __syncthreads();
}

// ---------- fused LN1 + LIF + qkv gather (fp8,half2) + q/k/v LIF ---------
__global__ void __launch_bounds__(512,2) k_qkv(
        const float* __restrict__ ln1_g, const float* __restrict__ ln1_b,
        const float* __restrict__ lifw,  const float* __restrict__ xt,
        unsigned char* __restrict__ qkvs){
    __shared__ unsigned mask[16];
    __shared__ int list[512];
    __shared__ int s_cnt;
    __shared__ float red[68];
    int bn = blockIdx.x;  int b = bn >> 8;  int n = bn & 255;
    int tid = threadIdx.x;
    float gg = ln1_g[tid], be = ln1_b[tid];
    float d1 = sigm(lifw[1]);
    float dq = sigm(lifw[2 + ((tid < 384) ? (tid >> 7) : 0)]);
    float vln = 0.f;
    float v0=0.f, v1=0.f, v2=0.f, v3=0.f;
    for (int t=0; t<T; t++){
        int tok = (t*Bb + b)*Nn + n;
        float xv = xt[(size_t)tok*C + tid];
        float2 sq = bsum2(xv, xv*xv, red, t & 1);
        float m  = sq.x * (1.f/512.f);
        float var = fmaxf(sq.y * (1.f/512.f) - m*m, 0.f);
        float y = (xv - m) * (1.f/sqrtf(var + 1e-5f)) * gg + be;
        vln = vln + (y - vln)*d1;
        int s = (vln >= 1.0f); if (s) vln = 0.f;
        unsigned bm = __ballot_sync(0xffffffffu, s);
        if ((tid & 31) == 0) mask[tid >> 5] = bm;
        __syncthreads();
        build_list(mask, list, &s_cnt);
        if (tid < 384){
            const unsigned char* wb = g_wq8 + (tid << 2);
            __half2 A = __float2half2_rn(0.f), B = __float2half2_rn(0.f);
            int cnt = s_cnt, i = 0;
            for (; i + 8 <= cnt; i += 8){
                unsigned u0 = *(const unsigned*)(wb + (size_t)list[i  ]*C3);
                unsigned u1 = *(const unsigned*)(wb + (size_t)list[i+1]*C3);
                unsigned u2 = *(const unsigned*)(wb + (size_t)list[i+2]*C3);
                unsigned u3 = *(const unsigned*)(wb + (size_t)list[i+3]*C3);
                unsigned u4 = *(const unsigned*)(wb + (size_t)list[i+4]*C3);
                unsigned u5 = *(const unsigned*)(wb + (size_t)list[i+5]*C3);
                unsigned u6 = *(const unsigned*)(wb + (size_t)list[i+6]*C3);
                unsigned u7 = *(const unsigned*)(wb + (size_t)list[i+7]*C3);
                acc8(u0,A,B); acc8(u1,A,B); acc8(u2,A,B); acc8(u3,A,B);
                acc8(u4,A,B); acc8(u5,A,B); acc8(u6,A,B); acc8(u7,A,B);
            }
            for (; i < cnt; i++){
                unsigned u = *(const unsigned*)(wb + (size_t)list[i]*C3);
                acc8(u,A,B);
            }
            float2 f01 = __half22float2(A);
            float2 f23 = __half22float2(B);
            v0 = v0 + (f01.x - v0)*dq;  v1 = v1 + (f01.y - v1)*dq;
            v2 = v2 + (f23.x - v2)*dq;  v3 = v3 + (f23.y - v3)*dq;
            uchar4 sc;
            sc.x = (v0 >= 1.0f); if (sc.x) v0 = 0.f;
            sc.y = (v1 >= 1.0f); if (sc.y) v1 = 0.f;
            sc.z = (v2 >= 1.0f); if (sc.z) v2 = 0.f;
            sc.w = (v3 >= 1.0f); if (sc.w) v3 = 0.f;
            *reinterpret_cast<uchar4*>(qkvs + (size_t)tok*C3 + (tid<<2)) = sc;
        }
        __syncthreads();
    }
}

// ---------- exact integer linear attention (smem-staged loads) -----------
__global__ void k_attn(const unsigned char* __restrict__ qkvs, float* __restrict__ attn){
    __shared__ int4 stage[1024];            // 256 tokens x 64B
    __shared__ unsigned kcol[Dd][8];
    __shared__ unsigned vcol[Dd][8];
    __shared__ int kvs[Dd*Dd];
    int bx = blockIdx.x;
    int hd = bx & 7;  int b = (bx >> 3) & 15;  int t = bx >> 7;
    int tid = threadIdx.x;
    int tbase = (t*Bb + b)*Nn;
    const unsigned char* base = qkvs + (size_t)tbase*C3;
    const unsigned char* sb = (const unsigned char*)stage;
    int koff = C + hd*Dd, voff = 2*C + hd*Dd, qoff = hd*Dd;

    for (int i=tid; i<1024; i+=256){
        int nn = i >> 2, ch = i & 3;
        stage[i] = *reinterpret_cast<const int4*>(base + (size_t)nn*C3 + koff + ch*16);
    }
    __syncthreads();
    for (int s=tid; s<512; s+=256){
        int e = s >> 3, w = s & 7;
        unsigned kb = 0;
        #pragma unroll 4
        for (int i=0;i<32;i++) kb |= ((unsigned)(sb[(w*32+i)*64 + e] != 0)) << i;
        kcol[e][w] = kb;
    }
    __syncthreads();
    for (int i=tid; i<1024; i+=256){
        int nn = i >> 2, ch = i & 3;
        stage[i] = *reinterpret_cast<const int4*>(base + (size_t)nn*C3 + voff + ch*16);
    }
    __syncthreads();
    for (int s=tid; s<512; s+=256){
        int e = s >> 3, w = s & 7;
        unsigned vb = 0;
        #pragma unroll 4
        for (int i=0;i<32;i++) vb |= ((unsigned)(sb[(w*32+i)*64 + e] != 0)) << i;
        vcol[e][w] = vb;
    }
    __syncthreads();
    for (int s=tid; s<Dd*Dd; s+=256){
        int e = s >> 6, f = s & 63;
        int sum = 0;
        #pragma unroll
        for (int w=0; w<8; w++) sum += __popc(kcol[e][w] & vcol[f][w]);
        kvs[s] = sum;
    }
    __syncthreads();
    for (int i=tid; i<1024; i+=256){
        int nn = i >> 2, ch = i & 3;
        stage[i] = *reinterpret_cast<const int4*>(base + (size_t)nn*C3 + qoff + ch*16);
    }
    __syncthreads();
    int n = tid;
    unsigned qb0=0, qb1=0;
    #pragma unroll 4
    for (int i=0;i<32;i++){
        qb0 |= ((unsigned)(sb[n*64 + i]      != 0)) << i;
        qb1 |= ((unsigned)(sb[n*64 + 32 + i] != 0)) << i;
    }
    int acc[Dd];
    #pragma unroll
    for (int f=0; f<Dd; f++) acc[f] = 0;
    unsigned m = qb0;
    while (m){
        int e = __ffs(m) - 1;  m &= m - 1;
        const int* kr = kvs + e*Dd;
        #pragma unroll
        for (int f=0; f<Dd; f++) acc[f] += kr[f];
    }
    m = qb1;
    while (m){
        int e = __ffs(m) + 31;  m &= m - 1;
        const int* kr = kvs + e*Dd;
        #pragma unroll
        for (int f=0; f<Dd; f++) acc[f] += kr[f];
    }
    float* outp = attn + (size_t)(tbase + n)*C + hd*Dd;
    #pragma unroll
    for (int f=0; f<Dd; f++) outp[f] = (float)acc[f] * 0.125f;
}

// ---------- fused tail: attnLIF+proj+res + LN2+LIF+fc1+hidLIF+fc2+res ----
__global__ void __launch_bounds__(512,2) k_tail(
        const float* __restrict__ lifw, const float* __restrict__ proj_b,
        const float* __restrict__ ln2_g, const float* __restrict__ ln2_b,
        const float* __restrict__ fc1_b, const float* __restrict__ fc2_b,
        const float* __restrict__ attn, float* __restrict__ xt){
    __shared__ unsigned mask[16];
    __shared__ unsigned mask2[64];
    __shared__ int list[512];
    __shared__ int s_cnt;
    __shared__ float red[68];
    int bn = blockIdx.x;  int b = bn >> 8;  int n = bn & 255;
    int tid = threadIdx.x;
    int lane = tid & 31, wrp = tid >> 5;
    float pb = proj_b[tid];
    float gg = ln2_g[tid], be = ln2_b[tid];
    float fb0 = fc1_b[tid*4], fb1 = fc1_b[tid*4+1], fb2 = fc1_b[tid*4+2], fb3 = fc1_b[tid*4+3];
    float f2b = fc2_b[tid];
    float d5 = sigm(lifw[5]), d6 = sigm(lifw[6]), d7 = sigm(lifw[7]);
    float v5 = 0.f, vln = 0.f;
    float h0=0.f, h1=0.f, h2=0.f, h3=0.f;
    for (int t=0; t<T; t++){
        int tok = (t*Bb + b)*Nn + n;
        // --- attn LIF + proj gather + residual ---
        float av = attn[(size_t)tok*C + tid];
        v5 = v5 + (av - v5)*d5;
        int s5 = (v5 >= 1.0f); if (s5) v5 = 0.f;
        unsigned bm = __ballot_sync(0xffffffffu, s5);
        if (lane == 0) mask[wrp] = bm;
        __syncthreads();
        build_list(mask, list, &s_cnt);
        float xv = xt[(size_t)tok*C + tid];
        {
            int cnt = s_cnt;
            for (int i=0; i<cnt; i++)
                xv += __bfloat162float(g_wp[(size_t)list[i]*C + tid]);
        }
        xv += pb;
        __syncthreads();
        // --- LN2 + LIF (single-pass) ---
        float2 sq = bsum2(xv, xv*xv, red, t & 1);
        float m  = sq.x * (1.f/512.f);
        float var = fmaxf(sq.y * (1.f/512.f) - m*m, 0.f);
        float y = (xv - m) * (1.f/sqrtf(var + 1e-5f)) * gg + be;
        vln = vln + (y - vln)*d6;
        int s6 = (vln >= 1.0f); if (s6) vln = 0.f;
        bm = __ballot_sync(0xffffffffu, s6);
        if (lane == 0) mask[wrp] = bm;
        __syncthreads();
        build_list(mask, list, &s_cnt);
        // --- fc1 gather (fp8, half2) ---
        float a0, a1, a2, a3;
        {
            const unsigned char* wb = g_wf18 + (tid << 2);
            __half2 A = __float2half2_rn(0.f), B = __float2half2_rn(0.f);
            int cnt = s_cnt, i = 0;
            for (; i + 8 <= cnt; i += 8){
                unsigned u0 = *(const unsigned*)(wb + (size_t)list[i  ]*HID);
                unsigned u1 = *(const unsigned*)(wb + (size_t)list[i+1]*HID);
                unsigned u2 = *(const unsigned*)(wb + (size_t)list[i+2]*HID);
                unsigned u3 = *(const unsigned*)(wb + (size_t)list[i+3]*HID);
                unsigned u4 = *(const unsigned*)(wb + (size_t)list[i+4]*HID);
                unsigned u5 = *(const unsigned*)(wb + (size_t)list[i+5]*HID);
                unsigned u6 = *(const unsigned*)(wb + (size_t)list[i+6]*HID);
                unsigned u7 = *(const unsigned*)(wb + (size_t)list[i+7]*HID);
                acc8(u0,A,B); acc8(u1,A,B); acc8(u2,A,B); acc8(u3,A,B);
                acc8(u4,A,B); acc8(u5,A,B); acc8(u6,A,B); acc8(u7,A,B);
            }
            for (; i < cnt; i++){
                unsigned u = *(const unsigned*)(wb + (size_t)list[i]*HID);
                acc8(u,A,B);
            }
            float2 f01 = __half22float2(A);
            float2 f23 = __half22float2(B);
            a0 = f01.x + fb0; a1 = f01.y + fb1; a2 = f23.x + fb2; a3 = f23.y + fb3;
        }
        // --- hidden LIF ---
        h0 = h0 + (a0 - h0)*d7;  h1 = h1 + (a1 - h1)*d7;
        h2 = h2 + (a2 - h2)*d7;  h3 = h3 + (a3 - h3)*d7;
        int t0 = (h0 >= 1.0f); if (t0) h0 = 0.f;
        int t1 = (h1 >= 1.0f); if (t1) h1 = 0.f;
        int t2 = (h2 >= 1.0f); if (t2) h2 = 0.f;
        int t3 = (h3 >= 1.0f); if (t3) h3 = 0.f;
        unsigned b0 = __ballot_sync(0xffffffffu, t0);
        unsigned b1 = __ballot_sync(0xffffffffu, t1);
        unsigned b2 = __ballot_sync(0xffffffffu, t2);
        unsigned b3 = __ballot_sync(0xffffffffu, t3);
        if (lane == 0){
            mask2[wrp*4 + 0] = b0;  mask2[wrp*4 + 1] = b1;
            mask2[wrp*4 + 2] = b2;  mask2[wrp*4 + 3] = b3;
        }
        __syncthreads();
        // --- fc2 gather (bf16) + residual, write final row ---
        float o = 0.f;
        for (int w64 = 0; w64 < 64; w64++){
            unsigned mv = mask2[w64];
            int ww = w64 >> 2, bb = w64 & 3;
            while (mv){
                int i = __ffs(mv) - 1;  mv &= mv - 1;
                int j = ww*128 + i*4 + bb;      // hidden index
                o += __bfloat162float(g_wf2[(size_t)j*C + tid]);
            }
        }
        xt[(size_t)tok*C + tid] = xv + o + f2b;
        __syncthreads();
    }
}

// ------------------------------- launch ----------------------------------
extern "C" void kernel_launch(void* const* d_in, const int* in_sizes, int n_in,
                              void* d_out, int out_size){
    const float* x      = (const float*)d_in[0];
    const float* conv_w = (const float*)d_in[1];
    const float* conv_b = (const float*)d_in[2];
    const float* ln1_g  = (const float*)d_in[3];
    const float* ln1_b  = (const float*)d_in[4];
    const float* qkv_w  = (const float*)d_in[5];
    const float* proj_w = (const float*)d_in[6];
    const float* proj_b = (const float*)d_in[7];
    const float* ln2_g  = (const float*)d_in[8];
    const float* ln2_b  = (const float*)d_in[9];
    const float* fc1_w  = (const float*)d_in[10];
    const float* fc1_b  = (const float*)d_in[11];
    const float* fc2_w  = (const float*)d_in[12];
    const float* fc2_b  = (const float*)d_in[13];
    const float* lifw   = (const float*)d_in[14];
    float* out = (float*)d_out;

    float *p_xc, *p_xt, *p_attn;
    unsigned char* p_qkvs;
    cudaGetSymbolAddress((void**)&p_xc,   g_xc);
    cudaGetSymbolAddress((void**)&p_xt,   g_xt);
    cudaGetSymbolAddress((void**)&p_attn, g_attn);
    cudaGetSymbolAddress((void**)&p_qkvs, g_qkvs);

    dim3 tb32(32,32);
    // 0) all weight transposes in one launch
    k_wt_all<<<3072, tb32>>>(qkv_w, proj_w, fc1_w, fc2_w);
    // 1) fused lif(x) + depthwise conv + residual
    k_convf<<<Bb*C, 256>>>(x, conv_w, conv_b, lifw, p_xc);
    // 2) [C,HW] -> [N,C] token layout
    k_tr<<<dim3(Nn/32, C/32, TB), tb32>>>(p_xc, p_xt, C, Nn);
    // 3) fused LN1 + LIF + qkv gather (fp8,half2) + q/k/v LIF
    k_qkv<<<BN, 512>>>(ln1_g, ln1_b, lifw, p_xt, p_qkvs);
    // 4) exact integer linear attention
    k_attn<<<T*Bb*NH, 256>>>(p_qkvs, p_attn);
    // 5) fused tail: attn LIF + proj + residual + LN2 + MLP + residual
    k_tail<<<BN, 512>>>(lifw, proj_b, ln2_g, ln2_b, fc1_b, fc2_b, p_attn, p_xt);
    // 6) [N,C] -> [C,HW] output layout
    k_tr<<<dim3(C/32, Nn/32, TB), tb32>>>(p_xt, out, Nn, C);
}

// round 15
// speedup vs baseline: 1.2616x; 1.2616x over previous
#include <cuda_runtime.h>
#include <cuda_bf16.h>
#include <cuda_fp8.h>
#include <math.h>

#define T  4
#define Bb 16
#define C  512
#define HW 256
#define Nn 256
#define C3 1536
#define HID 2048
#define NH 8
#define Dd 64
#define TB (T*Bb)            // 64
#define BN (Bb*Nn)           // 4096
#define TBN (T*Bb*Nn)        // 16384
#define XSZ (T*Bb*C*HW)      // 8388608

// ---------------- scratch (no cudaMalloc allowed) ----------------
__device__ float         g_xc[XSZ];       // x + pos         [T,B,C,HW]
__device__ float         g_xt[XSZ];       // residual stream [T,B,N,C]
__device__ unsigned char g_qkvs[TBN*C3];  // q/k/v spikes    [T,B,N,3C]
__device__ float         g_attn[XSZ];     // attn out        [T,B,N,C]
__device__ __align__(16) unsigned char g_wq8 [C*C3];   // fp8 [cin][3C]
__device__ __align__(16) unsigned char g_wf18[C*HID];  // fp8 [cin][HID]
__device__ __align__(16) __nv_bfloat16 g_wp [C*C];     // bf16 [cin][C]
__device__ __align__(16) __nv_bfloat16 g_wf2[HID*C];   // bf16 [hid][C]

__device__ __forceinline__ float sigm(float w){ return 1.f/(1.f+expf(-w)); }

__device__ __forceinline__ float4 fp8x4_to_f4(unsigned u){
    __half2_raw h0 = __nv_cvt_fp8x2_to_halfraw2((__nv_fp8x2_storage_t)(u & 0xFFFFu), __NV_E4M3);
    __half2_raw h1 = __nv_cvt_fp8x2_to_halfraw2((__nv_fp8x2_storage_t)(u >> 16),     __NV_E4M3);
    __half2 a = *reinterpret_cast<__half2*>(&h0);
    __half2 b = *reinterpret_cast<__half2*>(&h1);
    float2 fa = __half22float2(a), fb = __half22float2(b);
    return make_float4(fa.x, fa.y, fb.x, fb.y);
}

// ---------- single kernel: all 4 weight transposes (fp32 -> fp8/bf16) ----
__global__ void k_wt_all(const float* __restrict__ qkv_w, const float* __restrict__ proj_w,
                         const float* __restrict__ fc1_w, const float* __restrict__ fc2_w){
    __shared__ float tile[32][33];
    int bid = blockIdx.x;
    const float* src;  int nR, nC, local, mode;
    if      (bid < 768) { src = qkv_w;  nR = 1536; nC = 512;  local = bid;        mode = 0; }
    else if (bid < 1024){ src = proj_w; nR = 512;  nC = 512;  local = bid - 768;  mode = 1; }
    else if (bid < 2048){ src = fc1_w;  nR = 2048; nC = 512;  local = bid - 1024; mode = 2; }
    else                { src = fc2_w;  nR = 512;  nC = 2048; local = bid - 2048; mode = 3; }
    int tpr = nC >> 5;
    int tx = local % tpr, ty = local / tpr;
    int cx = tx*32 + threadIdx.x;
    int ry = ty*32 + threadIdx.y;
    tile[threadIdx.y][threadIdx.x] = src[(size_t)ry*nC + cx];
    __syncthreads();
    int ox = ty*32 + threadIdx.x;   // within nR
    int oy = tx*32 + threadIdx.y;   // within nC
    float v = tile[threadIdx.x][threadIdx.y];
    size_t di = (size_t)oy*nR + ox;
    if      (mode == 0) g_wq8 [di] = __nv_cvt_float_to_fp8(v, __NV_SATFINITE, __NV_E4M3);
    else if (mode == 1) g_wp  [di] = __float2bfloat16(v);
    else if (mode == 2) g_wf18[di] = __nv_cvt_float_to_fp8(v, __NV_SATFINITE, __NV_E4M3);
    else                g_wf2 [di] = __float2bfloat16(v);
}

// ---------- fused lif(x) + depthwise 3x3 conv + residual -----------------
__global__ void k_convf(const float* __restrict__ x, const float* __restrict__ conv_w,
                        const float* __restrict__ conv_b, const float* __restrict__ lifw,
                        float* __restrict__ xc){
    __shared__ float xs[T][324];
    __shared__ unsigned char ss[T][324];
    int bc = blockIdx.x;  int b = bc >> 9;  int c = bc & 511;
    int tid = threadIdx.x;
    float decay = sigm(lifw[0]);
    for (int i = tid; i < 324; i += 256){
        int y = i/18 - 1, xx = i%18 - 1;
        bool in = (y>=0 && y<16 && xx>=0 && xx<16);
        int p = y*16 + xx;
        #pragma unroll
        for (int t=0; t<T; t++)
            xs[t][i] = in ? x[((size_t)(t*Bb+b)*C + c)*HW + p] : 0.f;
    }
    __syncthreads();
    for (int i = tid; i < 324; i += 256){
        float v = 0.f;
        #pragma unroll
        for (int t=0; t<T; t++){
            float xv = xs[t][i];
            v = v + (xv - v)*decay;
            unsigned char s = (v >= 1.0f);
            if (s) v = 0.f;
            ss[t][i] = s;
        }
    }
    __syncthreads();
    int py = tid >> 4, px = tid & 15;
    float w[9];
    #pragma unroll
    for (int j=0;j<9;j++) w[j] = conv_w[c*9 + j];
    float cb = conv_b[c];
    #pragma unroll
    for (int t=0; t<T; t++){
        float acc = 0.f;
        #pragma unroll
        for (int ky=0; ky<3; ky++)
            #pragma unroll
            for (int kx=0; kx<3; kx++)
                acc += (float)ss[t][(py+ky)*18 + px+kx] * w[ky*3+kx];
        xc[((size_t)(t*Bb+b)*C + c)*HW + tid] = xs[t][(py+1)*18 + px+1] + acc + cb;
    }
}

// ---------- batched 2D fp32 transpose (per z-slice) ----------------------
__global__ void k_tr(const float* __restrict__ src, float* __restrict__ dst,
                     int rows, int cols){
    __shared__ float tile[32][33];
    int z = blockIdx.z;
    const float* s = src + (size_t)z*rows*cols;
    float*       d = dst + (size_t)z*rows*cols;
    int xx = blockIdx.x*32 + threadIdx.x;
    int yy = blockIdx.y*32 + threadIdx.y;
    tile[threadIdx.y][threadIdx.x] = s[(size_t)yy*cols + xx];
    __syncthreads();
    int x2 = blockIdx.y*32 + threadIdx.x;
    int y2 = blockIdx.x*32 + threadIdx.y;
    d[(size_t)y2*rows + x2] = tile[threadIdx.x][threadIdx.y];
}

// ---------- block-wide sum over 512 threads ------------------------------
__device__ __forceinline__ float bsum(float v, float* red){
    #pragma unroll
    for (int off=16; off; off>>=1) v += __shfl_down_sync(0xffffffffu, v, off);
    int lane = threadIdx.x & 31, w = threadIdx.x >> 5;
    if (lane==0) red[w] = v;
    __syncthreads();
    if (w==0){
        float s = (lane < 16) ? red[lane] : 0.f;
        #pragma unroll
        for (int off=8; off; off>>=1) s += __shfl_down_sync(0xffffffffu, s, off);
        if (lane==0) red[16] = s;
    }
    __syncthreads();
    float r = red[16];
    __syncthreads();
    return r;
}

// warp-0 builds ordered active-channel list from 16-word mask -------------
__device__ __forceinline__ void build_list(const unsigned* mask, int* list, int* s_cnt){
    int tid = threadIdx.x;
    if (tid < 32){
        unsigned wv = (tid < 16) ? mask[tid] : 0u;
        int c = __popc(wv);
        int inc = c;
        #pragma unroll
        for (int off=1; off<32; off<<=1){
            int v = __shfl_up_sync(0xffffffffu, inc, off);
            if (tid >= off) inc += v;
        }
        int idx = inc - c;
        while (wv){ int b = __ffs(wv)-1; wv &= wv-1; list[idx++] = (tid<<5) + b; }
        if (tid == 31) *s_cnt = inc;
    }
    __syncthreads();
}

// ---------- fused LN1 + LIF + qkv gather (fp8) + q/k/v LIF ---------------
__global__ void __launch_bounds__(512) k_qkv(
        const float* __restrict__ ln1_g, const float* __restrict__ ln1_b,
        const float* __restrict__ lifw,  const float* __restrict__ xt,
        unsigned char* __restrict__ qkvs){
    __shared__ unsigned mask[16];
    __shared__ int list[512];
    __shared__ int s_cnt;
    __shared__ float red[17];
    int bn = blockIdx.x;  int b = bn >> 8;  int n = bn & 255;
    int tid = threadIdx.x;
    float gg = ln1_g[tid], be = ln1_b[tid];
    float d1 = sigm(lifw[1]);
    float dq = sigm(lifw[2 + ((tid < 384) ? (tid >> 7) : 0)]);
    float vln = 0.f;
    float v0=0.f, v1=0.f, v2=0.f, v3=0.f;
    for (int t=0; t<T; t++){
        int tok = (t*Bb + b)*Nn + n;
        float xv = xt[(size_t)tok*C + tid];
        float m  = bsum(xv, red) * (1.f/512.f);
        float d  = xv - m;
        float var = bsum(d*d, red) * (1.f/512.f);
        float y = d * (1.f/sqrtf(var + 1e-5f)) * gg + be;
        vln = vln + (y - vln)*d1;
        int s = (vln >= 1.0f); if (s) vln = 0.f;
        unsigned bm = __ballot_sync(0xffffffffu, s);
        if ((tid & 31) == 0) mask[tid >> 5] = bm;
        __syncthreads();
        build_list(mask, list, &s_cnt);
        if (tid < 384){
            const unsigned char* wb = g_wq8 + (tid << 2);
            float a0=0.f, a1=0.f, a2=0.f, a3=0.f;
            int cnt = s_cnt, i = 0;
            for (; i + 4 <= cnt; i += 4){
                unsigned u0 = *(const unsigned*)(wb + (size_t)list[i  ]*C3);
                unsigned u1 = *(const unsigned*)(wb + (size_t)list[i+1]*C3);
                unsigned u2 = *(const unsigned*)(wb + (size_t)list[i+2]*C3);
                unsigned u3 = *(const unsigned*)(wb + (size_t)list[i+3]*C3);
                float4 f0 = fp8x4_to_f4(u0), f1 = fp8x4_to_f4(u1);
                float4 f2 = fp8x4_to_f4(u2), f3 = fp8x4_to_f4(u3);
                a0 += f0.x; a1 += f0.y; a2 += f0.z; a3 += f0.w;
                a0 += f1.x; a1 += f1.y; a2 += f1.z; a3 += f1.w;
                a0 += f2.x; a1 += f2.y; a2 += f2.z; a3 += f2.w;
                a0 += f3.x; a1 += f3.y; a2 += f3.z; a3 += f3.w;
            }
            for (; i < cnt; i++){
                unsigned u = *(const unsigned*)(wb + (size_t)list[i]*C3);
                float4 f = fp8x4_to_f4(u);
                a0 += f.x; a1 += f.y; a2 += f.z; a3 += f.w;
            }
            v0 = v0 + (a0 - v0)*dq;  v1 = v1 + (a1 - v1)*dq;
            v2 = v2 + (a2 - v2)*dq;  v3 = v3 + (a3 - v3)*dq;
            uchar4 sc;
            sc.x = (v0 >= 1.0f); if (sc.x) v0 = 0.f;
            sc.y = (v1 >= 1.0f); if (sc.y) v1 = 0.f;
            sc.z = (v2 >= 1.0f); if (sc.z) v2 = 0.f;
            sc.w = (v3 >= 1.0f); if (sc.w) v3 = 0.f;
            *reinterpret_cast<uchar4*>(qkvs + (size_t)tok*C3 + (tid<<2)) = sc;
        }
        __syncthreads();
    }
}

// ---------- exact integer linear attention (ballot masks, no conflicts) --
__global__ void __launch_bounds__(256) k_attn(
        const unsigned char* __restrict__ qkvs, float* __restrict__ attn){
    __shared__ unsigned kcol[Dd][8];
    __shared__ unsigned vcol[Dd][8];
    __shared__ int kvs[Dd*Dd];
    int bx = blockIdx.x;
    int hd = bx & 7;  int b = (bx >> 3) & 15;  int t = bx >> 7;
    int tid = threadIdx.x;
    int lane = tid & 31, wrp = tid >> 5;
    int tbase = (t*Bb + b)*Nn;
    const unsigned char* row = qkvs + (size_t)(tbase + tid)*C3;   // this thread's token

    // --- K / V masks via warp ballots (thread = token, warp = 32 tokens) ---
    {
        const uint4* kp = (const uint4*)(row + C + hd*Dd);
        #pragma unroll
        for (int j=0; j<4; j++){
            uint4 u4 = kp[j];
            unsigned wd[4] = {u4.x, u4.y, u4.z, u4.w};
            #pragma unroll
            for (int w4=0; w4<4; w4++){
                unsigned u = wd[w4];
                #pragma unroll
                for (int bp=0; bp<4; bp++){
                    unsigned bm = __ballot_sync(0xffffffffu, (u >> (8*bp)) & 0xFFu);
                    if (lane == 0) kcol[j*16 + w4*4 + bp][wrp] = bm;
                }
            }
        }
        const uint4* vp = (const uint4*)(row + 2*C + hd*Dd);
        #pragma unroll
        for (int j=0; j<4; j++){
            uint4 u4 = vp[j];
            unsigned wd[4] = {u4.x, u4.y, u4.z, u4.w};
            #pragma unroll
            for (int w4=0; w4<4; w4++){
                unsigned u = wd[w4];
                #pragma unroll
                for (int bp=0; bp<4; bp++){
                    unsigned bm = __ballot_sync(0xffffffffu, (u >> (8*bp)) & 0xFFu);
                    if (lane == 0) vcol[j*16 + w4*4 + bp][wrp] = bm;
                }
            }
        }
    }
    __syncthreads();
    // --- kv outer product: kv[e][f] = popc-sum over tokens ---
    for (int s=tid; s<Dd*Dd; s+=256){
        int e = s >> 6, f = s & 63;
        int sum = 0;
        #pragma unroll
        for (int w=0; w<8; w++) sum += __popc(kcol[e][w] & vcol[f][w]);
        kvs[s] = sum;
    }
    __syncthreads();
    // --- q bits for this token via packed byte-compare ---
    unsigned qb0 = 0, qb1 = 0;
    {
        const uint4* qp = (const uint4*)(row + hd*Dd);
        #pragma unroll
        for (int j=0; j<4; j++){
            uint4 u4 = qp[j];
            unsigned wd[4] = {u4.x, u4.y, u4.z, u4.w};
            #pragma unroll
            for (int w4=0; w4<4; w4++){
                unsigned mm = __vcmpne4(wd[w4], 0u);
                unsigned nib = ((mm & 0x01010101u) * 0x10204080u) >> 28;
                int ci = j*4 + w4;               // word index 0..15
                if (ci < 8) qb0 |= nib << (4*ci);
                else        qb1 |= nib << (4*(ci-8));
            }
        }
    }
    int acc[Dd];
    #pragma unroll
    for (int f=0; f<Dd; f++) acc[f] = 0;
    unsigned m = qb0;
    while (m){
        int e = __ffs(m) - 1;  m &= m - 1;
        const int* kr = kvs + e*Dd;
        #pragma unroll
        for (int f=0; f<Dd; f++) acc[f] += kr[f];
    }
    m = qb1;
    while (m){
        int e = __ffs(m) + 31;  m &= m - 1;
        const int* kr = kvs + e*Dd;
        #pragma unroll
        for (int f=0; f<Dd; f++) acc[f] += kr[f];
    }
    float4* outp = (float4*)(attn + (size_t)(tbase + tid)*C + hd*Dd);
    #pragma unroll
    for (int f4=0; f4<16; f4++){
        float4 o;
        o.x = (float)acc[f4*4+0] * 0.125f;
        o.y = (float)acc[f4*4+1] * 0.125f;
        o.z = (float)acc[f4*4+2] * 0.125f;
        o.w = (float)acc[f4*4+3] * 0.125f;
        outp[f4] = o;
    }
}

// ---------- fused tail: attnLIF+proj+res + LN2+LIF+fc1+hidLIF+fc2+res ----
__global__ void __launch_bounds__(512) k_tail(
        const float* __restrict__ lifw, const float* __restrict__ proj_b,
        const float* __restrict__ ln2_g, const float* __restrict__ ln2_b,
        const float* __restrict__ fc1_b, const float* __restrict__ fc2_b,
        const float* __restrict__ attn, float* __restrict__ xt){
    __shared__ unsigned mask[16];
    __shared__ unsigned mask2[64];
    __shared__ int list[512];
    __shared__ int s_cnt;
    __shared__ float red[17];
    int bn = blockIdx.x;  int b = bn >> 8;  int n = bn & 255;
    int tid = threadIdx.x;
    int lane = tid & 31, wrp = tid >> 5;
    float pb = proj_b[tid];
    float gg = ln2_g[tid], be = ln2_b[tid];
    float fb0 = fc1_b[tid*4], fb1 = fc1_b[tid*4+1], fb2 = fc1_b[tid*4+2], fb3 = fc1_b[tid*4+3];
    float f2b = fc2_b[tid];
    float d5 = sigm(lifw[5]), d6 = sigm(lifw[6]), d7 = sigm(lifw[7]);
    float v5 = 0.f, vln = 0.f;
    float h0=0.f, h1=0.f, h2=0.f, h3=0.f;
    for (int t=0; t<T; t++){
        int tok = (t*Bb + b)*Nn + n;
        // --- attn LIF + proj gather + residual ---
        float av = attn[(size_t)tok*C + tid];
        v5 = v5 + (av - v5)*d5;
        int s5 = (v5 >= 1.0f); if (s5) v5 = 0.f;
        unsigned bm = __ballot_sync(0xffffffffu, s5);
        if (lane == 0) mask[wrp] = bm;
        __syncthreads();
        build_list(mask, list, &s_cnt);
        float xv = xt[(size_t)tok*C + tid];
        {
            int cnt = s_cnt;
            for (int i=0; i<cnt; i++)
                xv += __bfloat162float(g_wp[(size_t)list[i]*C + tid]);
        }
        xv += pb;
        __syncthreads();
        // --- LN2 + LIF ---
        float m  = bsum(xv, red) * (1.f/512.f);
        float d  = xv - m;
        float var = bsum(d*d, red) * (1.f/512.f);
        float y = d * (1.f/sqrtf(var + 1e-5f)) * gg + be;
        vln = vln + (y - vln)*d6;
        int s6 = (vln >= 1.0f); if (s6) vln = 0.f;
        bm = __ballot_sync(0xffffffffu, s6);
        if (lane == 0) mask[wrp] = bm;
        __syncthreads();
        build_list(mask, list, &s_cnt);
        // --- fc1 gather (fp8) ---
        float a0=0.f, a1=0.f, a2=0.f, a3=0.f;
        {
            const unsigned char* wb = g_wf18 + (tid << 2);
            int cnt = s_cnt, i = 0;
            for (; i + 4 <= cnt; i += 4){
                unsigned u0 = *(const unsigned*)(wb + (size_t)list[i  ]*HID);
                unsigned u1 = *(const unsigned*)(wb + (size_t)list[i+1]*HID);
                unsigned u2 = *(const unsigned*)(wb + (size_t)list[i+2]*HID);
                unsigned u3 = *(const unsigned*)(wb + (size_t)list[i+3]*HID);
                float4 f0 = fp8x4_to_f4(u0), f1 = fp8x4_to_f4(u1);
                float4 f2 = fp8x4_to_f4(u2), f3 = fp8x4_to_f4(u3);
                a0 += f0.x; a1 += f0.y; a2 += f0.z; a3 += f0.w;
                a0 += f1.x; a1 += f1.y; a2 += f1.z; a3 += f1.w;
                a0 += f2.x; a1 += f2.y; a2 += f2.z; a3 += f2.w;
                a0 += f3.x; a1 += f3.y; a2 += f3.z; a3 += f3.w;
            }
            for (; i < cnt; i++){
                unsigned u = *(const unsigned*)(wb + (size_t)list[i]*HID);
                float4 f = fp8x4_to_f4(u);
                a0 += f.x; a1 += f.y; a2 += f.z; a3 += f.w;
            }
        }
        a0 += fb0; a1 += fb1; a2 += fb2; a3 += fb3;
        // --- hidden LIF ---
        h0 = h0 + (a0 - h0)*d7;  h1 = h1 + (a1 - h1)*d7;
        h2 = h2 + (a2 - h2)*d7;  h3 = h3 + (a3 - h3)*d7;
        int t0 = (h0 >= 1.0f); if (t0) h0 = 0.f;
        int t1 = (h1 >= 1.0f); if (t1) h1 = 0.f;
        int t2 = (h2 >= 1.0f); if (t2) h2 = 0.f;
        int t3 = (h3 >= 1.0f); if (t3) h3 = 0.f;
        unsigned b0 = __ballot_sync(0xffffffffu, t0);
        unsigned b1 = __ballot_sync(0xffffffffu, t1);
        unsigned b2 = __ballot_sync(0xffffffffu, t2);
        unsigned b3 = __ballot_sync(0xffffffffu, t3);
        if (lane == 0){
            mask2[wrp*4 + 0] = b0;  mask2[wrp*4 + 1] = b1;
            mask2[wrp*4 + 2] = b2;  mask2[wrp*4 + 3] = b3;
        }
        __syncthreads();
        // --- fc2 gather (bf16) + residual, write final row ---
        float o = 0.f;
        for (int w64 = 0; w64 < 64; w64++){
            unsigned mv = mask2[w64];
            int ww = w64 >> 2, bb = w64 & 3;
            while (mv){
                int i = __ffs(mv) - 1;  mv &= mv - 1;
                int j = ww*128 + i*4 + bb;      // hidden index
                o += __bfloat162float(g_wf2[(size_t)j*C + tid]);
            }
        }
        xt[(size_t)tok*C + tid] = xv + o + f2b;
        __syncthreads();
    }
}

// ------------------------------- launch ----------------------------------
extern "C" void kernel_launch(void* const* d_in, const int* in_sizes, int n_in,
                              void* d_out, int out_size){
    const float* x      = (const float*)d_in[0];
    const float* conv_w = (const float*)d_in[1];
    const float* conv_b = (const float*)d_in[2];
    const float* ln1_g  = (const float*)d_in[3];
    const float* ln1_b  = (const float*)d_in[4];
    const float* qkv_w  = (const float*)d_in[5];
    const float* proj_w = (const float*)d_in[6];
    const float* proj_b = (const float*)d_in[7];
    const float* ln2_g  = (const float*)d_in[8];
    const float* ln2_b  = (const float*)d_in[9];
    const float* fc1_w  = (const float*)d_in[10];
    const float* fc1_b  = (const float*)d_in[11];
    const float* fc2_w  = (const float*)d_in[12];
    const float* fc2_b  = (const float*)d_in[13];
    const float* lifw   = (const float*)d_in[14];
    float* out = (float*)d_out;

    float *p_xc, *p_xt, *p_attn;
    unsigned char* p_qkvs;
    cudaGetSymbolAddress((void**)&p_xc,   g_xc);
    cudaGetSymbolAddress((void**)&p_xt,   g_xt);
    cudaGetSymbolAddress((void**)&p_attn, g_attn);
    cudaGetSymbolAddress((void**)&p_qkvs, g_qkvs);

    dim3 tb32(32,32);
    // 0) all weight transposes in one launch
    k_wt_all<<<3072, tb32>>>(qkv_w, proj_w, fc1_w, fc2_w);
    // 1) fused lif(x) + depthwise conv + residual
    k_convf<<<Bb*C, 256>>>(x, conv_w, conv_b, lifw, p_xc);
    // 2) [C,HW] -> [N,C] token layout
    k_tr<<<dim3(Nn/32, C/32, TB), tb32>>>(p_xc, p_xt, C, Nn);
    // 3) fused LN1 + LIF + qkv gather (fp8) + q/k/v LIF
    k_qkv<<<BN, 512>>>(ln1_g, ln1_b, lifw, p_xt, p_qkvs);
    // 4) exact integer linear attention (ballot masks)
    k_attn<<<T*Bb*NH, 256>>>(p_qkvs, p_attn);
    // 5) fused tail: attn LIF + proj + residual + LN2 + MLP + residual
    k_tail<<<BN, 512>>>(lifw, proj_b, ln2_g, ln2_b, fc1_b, fc2_b, p_attn, p_xt);
    // 6) [N,C] -> [C,HW] output layout
    k_tr<<<dim3(C/32, Nn/32, TB), tb32>>>(p_xt, out, Nn, C);
}

// round 16
// speedup vs baseline: 1.3604x; 1.0783x over previous
#include <cuda_runtime.h>
#include <cuda_bf16.h>
#include <cuda_fp8.h>
#include <cuda_fp16.h>
#include <math.h>

#define T  4
#define Bb 16
#define C  512
#define HW 256
#define Nn 256
#define C3 1536
#define HID 2048
#define NH 8
#define Dd 64
#define TB (T*Bb)            // 64
#define BN (Bb*Nn)           // 4096
#define TBN (T*Bb*Nn)        // 16384
#define XSZ (T*Bb*C*HW)      // 8388608

// ---------------- scratch (no cudaMalloc allowed) ----------------
__device__ float         g_xc[XSZ];       // x + pos         [T,B,C,HW]
__device__ float         g_xt[XSZ];       // residual stream [T,B,N,C]
__device__ unsigned char g_qkvs[TBN*C3];  // q/k/v spikes    [T,B,N,3C]
__device__ short         g_attn[XSZ];     // attn counts     [T,B,N,C] (int16, exact)
__device__ __align__(16) unsigned char g_wq8 [C*C3];   // fp8 [cin][3C]
__device__ __align__(16) unsigned char g_wf18[C*HID];  // fp8 [cin][HID]
__device__ __align__(16) __nv_bfloat16 g_wp [C*C];     // bf16 [cin][C]
__device__ __align__(16) __nv_bfloat16 g_wf2[HID*C];   // bf16 [hid][C]

__device__ __forceinline__ float sigm(float w){ return 1.f/(1.f+expf(-w)); }

// accumulate 4 fp8 weights into two half2 accumulators (LDG+2CVT+2HADD2)
__device__ __forceinline__ void acc8(unsigned u, __half2& A, __half2& B){
    __half2_raw h0 = __nv_cvt_fp8x2_to_halfraw2((__nv_fp8x2_storage_t)(u & 0xFFFFu), __NV_E4M3);
    __half2_raw h1 = __nv_cvt_fp8x2_to_halfraw2((__nv_fp8x2_storage_t)(u >> 16),     __NV_E4M3);
    A = __hadd2(A, *reinterpret_cast<__half2*>(&h0));
    B = __hadd2(B, *reinterpret_cast<__half2*>(&h1));
}

// ---------- single kernel: all 4 weight transposes (fp32 -> fp8/bf16) ----
__global__ void k_wt_all(const float* __restrict__ qkv_w, const float* __restrict__ proj_w,
                         const float* __restrict__ fc1_w, const float* __restrict__ fc2_w){
    __shared__ float tile[32][33];
    int bid = blockIdx.x;
    const float* src;  int nR, nC, local, mode;
    if      (bid < 768) { src = qkv_w;  nR = 1536; nC = 512;  local = bid;        mode = 0; }
    else if (bid < 1024){ src = proj_w; nR = 512;  nC = 512;  local = bid - 768;  mode = 1; }
    else if (bid < 2048){ src = fc1_w;  nR = 2048; nC = 512;  local = bid - 1024; mode = 2; }
    else                { src = fc2_w;  nR = 512;  nC = 2048; local = bid - 2048; mode = 3; }
    int tpr = nC >> 5;
    int tx = local % tpr, ty = local / tpr;
    int cx = tx*32 + threadIdx.x;
    int ry = ty*32 + threadIdx.y;
    tile[threadIdx.y][threadIdx.x] = src[(size_t)ry*nC + cx];
    __syncthreads();
    int ox = ty*32 + threadIdx.x;   // within nR
    int oy = tx*32 + threadIdx.y;   // within nC
    float v = tile[threadIdx.x][threadIdx.y];
    size_t di = (size_t)oy*nR + ox;
    if      (mode == 0) g_wq8 [di] = __nv_cvt_float_to_fp8(v, __NV_SATFINITE, __NV_E4M3);
    else if (mode == 1) g_wp  [di] = __float2bfloat16(v);
    else if (mode == 2) g_wf18[di] = __nv_cvt_float_to_fp8(v, __NV_SATFINITE, __NV_E4M3);
    else                g_wf2 [di] = __float2bfloat16(v);
}

// ---------- fused lif(x) + depthwise 3x3 conv + residual -----------------
__global__ void k_convf(const float* __restrict__ x, const float* __restrict__ conv_w,
                        const float* __restrict__ conv_b, const float* __restrict__ lifw,
                        float* __restrict__ xc){
    __shared__ float xs[T][324];
    __shared__ unsigned char ss[T][324];
    int bc = blockIdx.x;  int b = bc >> 9;  int c = bc & 511;
    int tid = threadIdx.x;
    float decay = sigm(lifw[0]);
    for (int i = tid; i < 324; i += 256){
        int y = i/18 - 1, xx = i%18 - 1;
        bool in = (y>=0 && y<16 && xx>=0 && xx<16);
        int p = y*16 + xx;
        #pragma unroll
        for (int t=0; t<T; t++)
            xs[t][i] = in ? x[((size_t)(t*Bb+b)*C + c)*HW + p] : 0.f;
    }
    __syncthreads();
    for (int i = tid; i < 324; i += 256){
        float v = 0.f;
        #pragma unroll
        for (int t=0; t<T; t++){
            float xv = xs[t][i];
            v = v + (xv - v)*decay;
            unsigned char s = (v >= 1.0f);
            if (s) v = 0.f;
            ss[t][i] = s;
        }
    }
    __syncthreads();
    int py = tid >> 4, px = tid & 15;
    float w[9];
    #pragma unroll
    for (int j=0;j<9;j++) w[j] = conv_w[c*9 + j];
    float cb = conv_b[c];
    #pragma unroll
    for (int t=0; t<T; t++){
        float acc = 0.f;
        #pragma unroll
        for (int ky=0; ky<3; ky++)
            #pragma unroll
            for (int kx=0; kx<3; kx++)
                acc += (float)ss[t][(py+ky)*18 + px+kx] * w[ky*3+kx];
        xc[((size_t)(t*Bb+b)*C + c)*HW + tid] = xs[t][(py+1)*18 + px+1] + acc + cb;
    }
}

// ---------- batched 2D fp32 transpose (per z-slice) ----------------------
__global__ void k_tr(const float* __restrict__ src, float* __restrict__ dst,
                     int rows, int cols){
    __shared__ float tile[32][33];
    int z = blockIdx.z;
    const float* s = src + (size_t)z*rows*cols;
    float*       d = dst + (size_t)z*rows*cols;
    int xx = blockIdx.x*32 + threadIdx.x;
    int yy = blockIdx.y*32 + threadIdx.y;
    tile[threadIdx.y][threadIdx.x] = s[(size_t)yy*cols + xx];
    __syncthreads();
    int x2 = blockIdx.y*32 + threadIdx.x;
    int y2 = blockIdx.x*32 + threadIdx.y;
    d[(size_t)y2*rows + x2] = tile[threadIdx.x][threadIdx.y];
}

// ---------- block-wide sum over 512 threads ------------------------------
__device__ __forceinline__ float bsum(float v, float* red){
    #pragma unroll
    for (int off=16; off; off>>=1) v += __shfl_down_sync(0xffffffffu, v, off);
    int lane = threadIdx.x & 31, w = threadIdx.x >> 5;
    if (lane==0) red[w] = v;
    __syncthreads();
    if (w==0){
        float s = (lane < 16) ? red[lane] : 0.f;
        #pragma unroll
        for (int off=8; off; off>>=1) s += __shfl_down_sync(0xffffffffu, s, off);
        if (lane==0) red[16] = s;
    }
    __syncthreads();
    float r = red[16];
    __syncthreads();
    return r;
}

// warp-0 builds ordered active-channel list (entries scaled by mult) ------
__device__ __forceinline__ void build_list(const unsigned* mask, int* list, int* s_cnt,
                                           int mult){
    int tid = threadIdx.x;
    if (tid < 32){
        unsigned wv = (tid < 16) ? mask[tid] : 0u;
        int c = __popc(wv);
        int inc = c;
        #pragma unroll
        for (int off=1; off<32; off<<=1){
            int v = __shfl_up_sync(0xffffffffu, inc, off);
            if (tid >= off) inc += v;
        }
        int idx = inc - c;
        while (wv){ int b = __ffs(wv)-1; wv &= wv-1; list[idx++] = ((tid<<5) + b)*mult; }
        if (tid == 31) *s_cnt = inc;
    }
    __syncthreads();
}

// ---------- fused LN1 + LIF + qkv gather (fp8,half2) + q/k/v LIF ---------
__global__ void __launch_bounds__(512) k_qkv(
        const float* __restrict__ ln1_g, const float* __restrict__ ln1_b,
        const float* __restrict__ lifw,  const float* __restrict__ xt,
        unsigned char* __restrict__ qkvs){
    __shared__ unsigned mask[16];
    __shared__ int list[512];
    __shared__ int s_cnt;
    __shared__ float red[17];
    int bn = blockIdx.x;  int b = bn >> 8;  int n = bn & 255;
    int tid = threadIdx.x;
    float gg = ln1_g[tid], be = ln1_b[tid];
    float d1 = sigm(lifw[1]);
    float dq = sigm(lifw[2 + ((tid < 384) ? (tid >> 7) : 0)]);
    float vln = 0.f;
    float v0=0.f, v1=0.f, v2=0.f, v3=0.f;
    for (int t=0; t<T; t++){
        int tok = (t*Bb + b)*Nn + n;
        float xv = xt[(size_t)tok*C + tid];
        float m  = bsum(xv, red) * (1.f/512.f);
        float d  = xv - m;
        float var = bsum(d*d, red) * (1.f/512.f);
        float y = d * (1.f/sqrtf(var + 1e-5f)) * gg + be;
        vln = vln + (y - vln)*d1;
        int s = (vln >= 1.0f); if (s) vln = 0.f;
        unsigned bm = __ballot_sync(0xffffffffu, s);
        if ((tid & 31) == 0) mask[tid >> 5] = bm;
        __syncthreads();
        build_list(mask, list, &s_cnt, C3);      // entries are byte offsets
        if (tid < 384){
            const unsigned char* wb = g_wq8 + (tid << 2);
            __half2 A = __float2half2_rn(0.f), B = __float2half2_rn(0.f);
            int cnt = s_cnt, i = 0;
            for (; i + 4 <= cnt; i += 4){
                unsigned u0 = *(const unsigned*)(wb + list[i  ]);
                unsigned u1 = *(const unsigned*)(wb + list[i+1]);
                unsigned u2 = *(const unsigned*)(wb + list[i+2]);
                unsigned u3 = *(const unsigned*)(wb + list[i+3]);
                acc8(u0,A,B); acc8(u1,A,B); acc8(u2,A,B); acc8(u3,A,B);
            }
            for (; i < cnt; i++){
                unsigned u = *(const unsigned*)(wb + list[i]);
                acc8(u,A,B);
            }
            float2 f01 = __half22float2(A);
            float2 f23 = __half22float2(B);
            v0 = v0 + (f01.x - v0)*dq;  v1 = v1 + (f01.y - v1)*dq;
            v2 = v2 + (f23.x - v2)*dq;  v3 = v3 + (f23.y - v3)*dq;
            uchar4 sc;
            sc.x = (v0 >= 1.0f); if (sc.x) v0 = 0.f;
            sc.y = (v1 >= 1.0f); if (sc.y) v1 = 0.f;
            sc.z = (v2 >= 1.0f); if (sc.z) v2 = 0.f;
            sc.w = (v3 >= 1.0f); if (sc.w) v3 = 0.f;
            *reinterpret_cast<uchar4*>(qkvs + (size_t)tok*C3 + (tid<<2)) = sc;
        }
        __syncthreads();
    }
}

// ---------- exact integer linear attention (ballot masks, int16 out) -----
__global__ void __launch_bounds__(256) k_attn(
        const unsigned char* __restrict__ qkvs, short* __restrict__ attn){
    __shared__ unsigned kcol[Dd][8];
    __shared__ unsigned vcol[Dd][8];
    __shared__ int kvs[Dd*Dd];
    int bx = blockIdx.x;
    int hd = bx & 7;  int b = (bx >> 3) & 15;  int t = bx >> 7;
    int tid = threadIdx.x;
    int lane = tid & 31, wrp = tid >> 5;
    int tbase = (t*Bb + b)*Nn;
    const unsigned char* row = qkvs + (size_t)(tbase + tid)*C3;   // this thread's token

    {
        const uint4* kp = (const uint4*)(row + C + hd*Dd);
        #pragma unroll
        for (int j=0; j<4; j++){
            uint4 u4 = kp[j];
            unsigned wd[4] = {u4.x, u4.y, u4.z, u4.w};
            #pragma unroll
            for (int w4=0; w4<4; w4++){
                unsigned u = wd[w4];
                #pragma unroll
                for (int bp=0; bp<4; bp++){
                    unsigned bm = __ballot_sync(0xffffffffu, (u >> (8*bp)) & 0xFFu);
                    if (lane == 0) kcol[j*16 + w4*4 + bp][wrp] = bm;
                }
            }
        }
        const uint4* vp = (const uint4*)(row + 2*C + hd*Dd);
        #pragma unroll
        for (int j=0; j<4; j++){
            uint4 u4 = vp[j];
            unsigned wd[4] = {u4.x, u4.y, u4.z, u4.w};
            #pragma unroll
            for (int w4=0; w4<4; w4++){
                unsigned u = wd[w4];
                #pragma unroll
                for (int bp=0; bp<4; bp++){
                    unsigned bm = __ballot_sync(0xffffffffu, (u >> (8*bp)) & 0xFFu);
                    if (lane == 0) vcol[j*16 + w4*4 + bp][wrp] = bm;
                }
            }
        }
    }
    __syncthreads();
    for (int s=tid; s<Dd*Dd; s+=256){
        int e = s >> 6, f = s & 63;
        int sum = 0;
        #pragma unroll
        for (int w=0; w<8; w++) sum += __popc(kcol[e][w] & vcol[f][w]);
        kvs[s] = sum;
    }
    __syncthreads();
    unsigned qb0 = 0, qb1 = 0;
    {
        const uint4* qp = (const uint4*)(row + hd*Dd);
        #pragma unroll
        for (int j=0; j<4; j++){
            uint4 u4 = qp[j];
            unsigned wd[4] = {u4.x, u4.y, u4.z, u4.w};
            #pragma unroll
            for (int w4=0; w4<4; w4++){
                unsigned mm = __vcmpne4(wd[w4], 0u);
                unsigned nib = ((mm & 0x01010101u) * 0x10204080u) >> 28;
                int ci = j*4 + w4;
                if (ci < 8) qb0 |= nib << (4*ci);
                else        qb1 |= nib << (4*(ci-8));
            }
        }
    }
    int acc[Dd];
    #pragma unroll
    for (int f=0; f<Dd; f++) acc[f] = 0;
    unsigned m = qb0;
    while (m){
        int e = __ffs(m) - 1;  m &= m - 1;
        const int* kr = kvs + e*Dd;
        #pragma unroll
        for (int f=0; f<Dd; f++) acc[f] += kr[f];
    }
    m = qb1;
    while (m){
        int e = __ffs(m) + 31;  m &= m - 1;
        const int* kr = kvs + e*Dd;
        #pragma unroll
        for (int f=0; f<Dd; f++) acc[f] += kr[f];
    }
    // pack 64 counts into 8 x int4 (16 shorts each... 8 shorts per int4)
    int4* outp = (int4*)(attn + (size_t)(tbase + tid)*C + hd*Dd);
    #pragma unroll
    for (int j=0; j<8; j++){
        int4 o;
        o.x = (acc[j*8+0] & 0xFFFF) | (acc[j*8+1] << 16);
        o.y = (acc[j*8+2] & 0xFFFF) | (acc[j*8+3] << 16);
        o.z = (acc[j*8+4] & 0xFFFF) | (acc[j*8+5] << 16);
        o.w = (acc[j*8+6] & 0xFFFF) | (acc[j*8+7] << 16);
        outp[j] = o;
    }
}

// ---------- fused tail: attnLIF+proj+res + LN2+LIF+fc1+hidLIF+fc2+res ----
__global__ void __launch_bounds__(512) k_tail(
        const float* __restrict__ lifw, const float* __restrict__ proj_b,
        const float* __restrict__ ln2_g, const float* __restrict__ ln2_b,
        const float* __restrict__ fc1_b, const float* __restrict__ fc2_b,
        const short* __restrict__ attn, float* __restrict__ xt){
    __shared__ unsigned mask[16];
    __shared__ unsigned mask2[64];
    __shared__ int list[512];
    __shared__ int s_cnt;
    __shared__ float red[17];
    int bn = blockIdx.x;  int b = bn >> 8;  int n = bn & 255;
    int tid = threadIdx.x;
    int lane = tid & 31, wrp = tid >> 5;
    float pb = proj_b[tid];
    float gg = ln2_g[tid], be = ln2_b[tid];
    float fb0 = fc1_b[tid*4], fb1 = fc1_b[tid*4+1], fb2 = fc1_b[tid*4+2], fb3 = fc1_b[tid*4+3];
    float f2b = fc2_b[tid];
    float d5 = sigm(lifw[5]), d6 = sigm(lifw[6]), d7 = sigm(lifw[7]);
    float v5 = 0.f, vln = 0.f;
    float h0=0.f, h1=0.f, h2=0.f, h3=0.f;
    for (int t=0; t<T; t++){
        int tok = (t*Bb + b)*Nn + n;
        // --- attn LIF + proj gather + residual ---
        float av = (float)attn[(size_t)tok*C + tid] * 0.125f;
        v5 = v5 + (av - v5)*d5;
        int s5 = (v5 >= 1.0f); if (s5) v5 = 0.f;
        unsigned bm = __ballot_sync(0xffffffffu, s5);
        if (lane == 0) mask[wrp] = bm;
        __syncthreads();
        build_list(mask, list, &s_cnt, 1);
        float xv = xt[(size_t)tok*C + tid];
        {
            int cnt = s_cnt;
            for (int i=0; i<cnt; i++)
                xv += __bfloat162float(g_wp[(size_t)list[i]*C + tid]);
        }
        xv += pb;
        __syncthreads();
        // --- LN2 + LIF ---
        float m  = bsum(xv, red) * (1.f/512.f);
        float d  = xv - m;
        float var = bsum(d*d, red) * (1.f/512.f);
        float y = d * (1.f/sqrtf(var + 1e-5f)) * gg + be;
        vln = vln + (y - vln)*d6;
        int s6 = (vln >= 1.0f); if (s6) vln = 0.f;
        bm = __ballot_sync(0xffffffffu, s6);
        if (lane == 0) mask[wrp] = bm;
        __syncthreads();
        build_list(mask, list, &s_cnt, HID);     // byte offsets into fc1 rows
        // --- fc1 gather (fp8, half2) ---
        float a0, a1, a2, a3;
        {
            const unsigned char* wb = g_wf18 + (tid << 2);
            __half2 A = __float2half2_rn(0.f), B = __float2half2_rn(0.f);
            int cnt = s_cnt, i = 0;
            for (; i + 4 <= cnt; i += 4){
                unsigned u0 = *(const unsigned*)(wb + list[i  ]);
                unsigned u1 = *(const unsigned*)(wb + list[i+1]);
                unsigned u2 = *(const unsigned*)(wb + list[i+2]);
                unsigned u3 = *(const unsigned*)(wb + list[i+3]);
                acc8(u0,A,B); acc8(u1,A,B); acc8(u2,A,B); acc8(u3,A,B);
            }
            for (; i < cnt; i++){
                unsigned u = *(const unsigned*)(wb + list[i]);
                acc8(u,A,B);
            }
            float2 f01 = __half22float2(A);
            float2 f23 = __half22float2(B);
            a0 = f01.x + fb0; a1 = f01.y + fb1; a2 = f23.x + fb2; a3 = f23.y + fb3;
        }
        // --- hidden LIF ---
        h0 = h0 + (a0 - h0)*d7;  h1 = h1 + (a1 - h1)*d7;
        h2 = h2 + (a2 - h2)*d7;  h3 = h3 + (a3 - h3)*d7;
        int t0 = (h0 >= 1.0f); if (t0) h0 = 0.f;
        int t1 = (h1 >= 1.0f); if (t1) h1 = 0.f;
        int t2 = (h2 >= 1.0f); if (t2) h2 = 0.f;
        int t3 = (h3 >= 1.0f); if (t3) h3 = 0.f;
        unsigned b0 = __ballot_sync(0xffffffffu, t0);
        unsigned b1 = __ballot_sync(0xffffffffu, t1);
        unsigned b2 = __ballot_sync(0xffffffffu, t2);
        unsigned b3 = __ballot_sync(0xffffffffu, t3);
        if (lane == 0){
            mask2[wrp*4 + 0] = b0;  mask2[wrp*4 + 1] = b1;
            mask2[wrp*4 + 2] = b2;  mask2[wrp*4 + 3] = b3;
        }
        __syncthreads();
        // --- fc2 gather (bf16) + residual, write final row ---
        float o = 0.f;
        for (int w64 = 0; w64 < 64; w64++){
            unsigned mv = mask2[w64];
            int ww = w64 >> 2, bb = w64 & 3;
            while (mv){
                int i = __ffs(mv) - 1;  mv &= mv - 1;
                int j = ww*128 + i*4 + bb;      // hidden index
                o += __bfloat162float(g_wf2[(size_t)j*C + tid]);
            }
        }
        xt[(size_t)tok*C + tid] = xv + o + f2b;
        __syncthreads();
    }
}

// ------------------------------- launch ----------------------------------
extern "C" void kernel_launch(void* const* d_in, const int* in_sizes, int n_in,
                              void* d_out, int out_size){
    const float* x      = (const float*)d_in[0];
    const float* conv_w = (const float*)d_in[1];
    const float* conv_b = (const float*)d_in[2];
    const float* ln1_g  = (const float*)d_in[3];
    const float* ln1_b  = (const float*)d_in[4];
    const float* qkv_w  = (const float*)d_in[5];
    const float* proj_w = (const float*)d_in[6];
    const float* proj_b = (const float*)d_in[7];
    const float* ln2_g  = (const float*)d_in[8];
    const float* ln2_b  = (const float*)d_in[9];
    const float* fc1_w  = (const float*)d_in[10];
    const float* fc1_b  = (const float*)d_in[11];
    const float* fc2_w  = (const float*)d_in[12];
    const float* fc2_b  = (const float*)d_in[13];
    const float* lifw   = (const float*)d_in[14];
    float* out = (float*)d_out;

    float *p_xc, *p_xt;
    short* p_attn;
    unsigned char* p_qkvs;
    cudaGetSymbolAddress((void**)&p_xc,   g_xc);
    cudaGetSymbolAddress((void**)&p_xt,   g_xt);
    cudaGetSymbolAddress((void**)&p_attn, g_attn);
    cudaGetSymbolAddress((void**)&p_qkvs, g_qkvs);

    dim3 tb32(32,32);
    // 0) all weight transposes in one launch
    k_wt_all<<<3072, tb32>>>(qkv_w, proj_w, fc1_w, fc2_w);
    // 1) fused lif(x) + depthwise conv + residual
    k_convf<<<Bb*C, 256>>>(x, conv_w, conv_b, lifw, p_xc);
    // 2) [C,HW] -> [N,C] token layout
    k_tr<<<dim3(Nn/32, C/32, TB), tb32>>>(p_xc, p_xt, C, Nn);
    // 3) fused LN1 + LIF + qkv gather (fp8, half2) + q/k/v LIF
    k_qkv<<<BN, 512>>>(ln1_g, ln1_b, lifw, p_xt, p_qkvs);
    // 4) exact integer linear attention (ballot masks, int16 out)
    k_attn<<<T*Bb*NH, 256>>>(p_qkvs, p_attn);
    // 5) fused tail: attn LIF + proj + residual + LN2 + MLP + residual
    k_tail<<<BN, 512>>>(lifw, proj_b, ln2_g, ln2_b, fc1_b, fc2_b, p_attn, p_xt);
    // 6) [N,C] -> [C,HW] output layout
    k_tr<<<dim3(C/32, Nn/32, TB), tb32>>>(p_xt, out, Nn, C);
}